// round 11
// baseline (speedup 1.0000x reference)
#include <cuda_runtime.h>
#include <cuda_bf16.h>
#include <cstdint>

#define BATCH 16
#define CHAN  64
#define NPTS  65536
#define RES   (32*32*32)   // 32768

// ---------------- scratch (device globals; no allocations allowed) ----------
__device__ float        g_meansum[BATCH * 3];
__device__ unsigned int g_maxnorm[BATCH];
__device__ int          g_voxidx[BATCH * NPTS];     // voxel index per point
__device__ int          g_counts[BATCH * RES];      // points per voxel
__device__ int          g_cnt2[BATCH * RES];        // rank counter for sort
__device__ int          g_offset[BATCH * RES];      // exclusive prefix of counts
__device__ int          g_pos[BATCH * NPTS];        // sorted slot per point
__device__ float        g_featT[(size_t)BATCH * NPTS * CHAN]; // sorted [b,pos,c]

// ---------------- kernel 0: zero counts + rank counters + stats --------------
__global__ void zero_counts_kernel() {
    int i = blockIdx.x * blockDim.x + threadIdx.x;   // 131072 threads
    reinterpret_cast<int4*>(g_counts)[i] = make_int4(0, 0, 0, 0);
    reinterpret_cast<int4*>(g_cnt2)[i]   = make_int4(0, 0, 0, 0);
    if (i < BATCH * 3) g_meansum[i] = 0.0f;
    if (i < BATCH)     g_maxnorm[i] = 0u;
}

// ---------------- kernel 1: per-batch coordinate mean (sum) ------------------
__global__ void mean_kernel(const float* __restrict__ coords) {
    int b = blockIdx.y;
    const float* cb = coords + (size_t)b * 3 * NPTS;
    float sx = 0.f, sy = 0.f, sz = 0.f;
    for (int n = blockIdx.x * blockDim.x + threadIdx.x; n < NPTS;
         n += gridDim.x * blockDim.x) {
        sx += cb[n];
        sy += cb[NPTS + n];
        sz += cb[2 * NPTS + n];
    }
    for (int o = 16; o > 0; o >>= 1) {
        sx += __shfl_down_sync(0xffffffffu, sx, o);
        sy += __shfl_down_sync(0xffffffffu, sy, o);
        sz += __shfl_down_sync(0xffffffffu, sz, o);
    }
    __shared__ float shx[8], shy[8], shz[8];
    int warp = threadIdx.x >> 5, lane = threadIdx.x & 31;
    if (lane == 0) { shx[warp] = sx; shy[warp] = sy; shz[warp] = sz; }
    __syncthreads();
    if (threadIdx.x == 0) {
        float tx = 0.f, ty = 0.f, tz = 0.f;
        int nw = blockDim.x >> 5;
        for (int w = 0; w < nw; w++) { tx += shx[w]; ty += shy[w]; tz += shz[w]; }
        atomicAdd(&g_meansum[b * 3 + 0], tx);
        atomicAdd(&g_meansum[b * 3 + 1], ty);
        atomicAdd(&g_meansum[b * 3 + 2], tz);
    }
}

// ---------------- kernel 2: per-batch max squared norm -----------------------
__global__ void maxnorm_kernel(const float* __restrict__ coords) {
    int b = blockIdx.y;
    const float* cb = coords + (size_t)b * 3 * NPTS;
    const float inv_n = 1.0f / (float)NPTS;
    float mx = g_meansum[b * 3 + 0] * inv_n;
    float my = g_meansum[b * 3 + 1] * inv_n;
    float mz = g_meansum[b * 3 + 2] * inv_n;
    float best = 0.f;
    for (int n = blockIdx.x * blockDim.x + threadIdx.x; n < NPTS;
         n += gridDim.x * blockDim.x) {
        float dx = cb[n] - mx;
        float dy = cb[NPTS + n] - my;
        float dz = cb[2 * NPTS + n] - mz;
        best = fmaxf(best, dx * dx + dy * dy + dz * dz);
    }
    for (int o = 16; o > 0; o >>= 1)
        best = fmaxf(best, __shfl_down_sync(0xffffffffu, best, o));
    __shared__ float sh[8];
    int warp = threadIdx.x >> 5, lane = threadIdx.x & 31;
    if (lane == 0) sh[warp] = best;
    __syncthreads();
    if (threadIdx.x == 0) {
        float t = 0.f;
        int nw = blockDim.x >> 5;
        for (int w = 0; w < nw; w++) t = fmaxf(t, sh[w]);
        atomicMax(&g_maxnorm[b], __float_as_uint(t));
    }
}

// ---------------- kernel 3: per-point normalize, norm_coords, voxidx, count --
__global__ void point_kernel(const float* __restrict__ coords,
                             float* __restrict__ norm_out) {
    int b = blockIdx.y;
    const float* cb = coords + (size_t)b * 3 * NPTS;
    float* nb = norm_out + (size_t)b * 3 * NPTS;
    const float inv_n = 1.0f / (float)NPTS;
    float mx = g_meansum[b * 3 + 0] * inv_n;
    float my = g_meansum[b * 3 + 1] * inv_n;
    float mz = g_meansum[b * 3 + 2] * inv_n;
    float inv_d = 1.0f / (sqrtf(__uint_as_float(g_maxnorm[b])) * 2.0f);

    for (int n = blockIdx.x * blockDim.x + threadIdx.x; n < NPTS;
         n += gridDim.x * blockDim.x) {
        float sx = ((cb[n]            - mx) * inv_d + 0.5f) * 32.0f;
        float sy = ((cb[NPTS + n]     - my) * inv_d + 0.5f) * 32.0f;
        float sz = ((cb[2 * NPTS + n] - mz) * inv_d + 0.5f) * 32.0f;
        sx = fminf(fmaxf(sx, 0.0f), 31.0f);
        sy = fminf(fmaxf(sy, 0.0f), 31.0f);
        sz = fminf(fmaxf(sz, 0.0f), 31.0f);
        nb[n]            = sx;
        nb[NPTS + n]     = sy;
        nb[2 * NPTS + n] = sz;
        int vx = (int)rintf(sx);   // round-half-even, matches jnp.round
        int vy = (int)rintf(sy);
        int vz = (int)rintf(sz);
        int idx = (vx << 10) + (vy << 5) + vz;
        g_voxidx[(b << 16) + n] = idx;
        atomicAdd(&g_counts[b * RES + idx], 1);
    }
}

// ---------------- kernel 4: per-batch exclusive scan of counts ---------------
__global__ void scan_kernel() {
    int b = blockIdx.x;
    int base = b * RES;
    int t = threadIdx.x;               // 1024 threads, 32 values each
    int local[32];
    int s = 0;
    #pragma unroll
    for (int i = 0; i < 32; i++) { local[i] = g_counts[base + t * 32 + i]; s += local[i]; }

    int lane = t & 31, warp = t >> 5;
    int incl = s;
    #pragma unroll
    for (int o = 1; o < 32; o <<= 1) {
        int x = __shfl_up_sync(0xffffffffu, incl, o);
        if (lane >= o) incl += x;
    }
    __shared__ int wsum[32];
    if (lane == 31) wsum[warp] = incl;
    __syncthreads();
    if (warp == 0) {
        int v = wsum[lane];
        #pragma unroll
        for (int o = 1; o < 32; o <<= 1) {
            int x = __shfl_up_sync(0xffffffffu, v, o);
            if (lane >= o) v += x;
        }
        wsum[lane] = v;
    }
    __syncthreads();
    int excl = incl - s + (warp > 0 ? wsum[warp - 1] : 0);
    int run = excl;
    #pragma unroll
    for (int i = 0; i < 32; i++) { g_offset[base + t * 32 + i] = run; run += local[i]; }
}

// ---------------- kernel 5: sorted position per point ------------------------
__global__ void pos_kernel() {
    int p = blockIdx.x * blockDim.x + threadIdx.x;   // BATCH*NPTS threads
    int b = p >> 16;
    int v = g_voxidx[p];
    int pos = g_offset[b * RES + v] + atomicAdd(&g_cnt2[b * RES + v], 1);
    g_pos[p] = pos;
}

// ---------------- kernel 6: fused transpose + sort: f[C,N] -> featT[pos,C] ---
__global__ void transposeT_kernel(const float* __restrict__ features) {
    __shared__ float tile[64][65];
    __shared__ int   pos_s[64];
    int b  = blockIdx.y;
    int n0 = blockIdx.x << 6;          // 64-point tile

    const float4* src = reinterpret_cast<const float4*>(
        features + (size_t)b * CHAN * NPTS + n0);
    const int row_f4 = NPTS / 4;       // float4 stride per channel row
    #pragma unroll
    for (int k = 0; k < 4; k++) {
        int idx = threadIdx.x + (k << 8);   // 0..1023
        int c  = idx >> 4;                  // channel 0..63
        int q  = idx & 15;                  // float4 within 64-point row
        float4 v = src[(size_t)c * row_f4 + q];
        int j = q << 2;
        tile[j + 0][c] = v.x;
        tile[j + 1][c] = v.y;
        tile[j + 2][c] = v.z;
        tile[j + 3][c] = v.w;
    }
    if (threadIdx.x < 64)
        pos_s[threadIdx.x] = g_pos[(b << 16) + n0 + threadIdx.x];
    __syncthreads();

    // write: half-warp per point, 16 lanes x float4 = 256B contiguous row
    int w    = threadIdx.x >> 5;
    int lane = threadIdx.x & 31;
    int half = lane >> 4;
    int c4   = lane & 15;
    #pragma unroll
    for (int k = 0; k < 4; k++) {
        int j = (w << 3) + (k << 1) + half;          // point 0..63
        float4 v;
        v.x = tile[j][(c4 << 2) + 0];
        v.y = tile[j][(c4 << 2) + 1];
        v.z = tile[j][(c4 << 2) + 2];
        v.w = tile[j][(c4 << 2) + 3];
        float4* dst = reinterpret_cast<float4*>(
            g_featT + (((size_t)(b << 16) + pos_s[j]) << 6));
        dst[c4] = v;
    }
}

// ---------------- kernel 7: segmented reduce + transpose-write ---------------
// block = (b, 32-voxel chunk); warp w owns voxels w*4..w*4+3; lane covers
// channels 2*lane, 2*lane+1 (float2 per row = 256B coalesced per warp).
__global__ void segreduce_kernel(float* __restrict__ out) {
    __shared__ float tile[32][65];
    __shared__ float inv[32];
    int chunk = blockIdx.x;            // 0 .. BATCH*1024-1
    int b  = chunk >> 10;
    int v0 = (chunk & 1023) << 5;

    int w    = threadIdx.x >> 5;
    int lane = threadIdx.x & 31;

    if (threadIdx.x < 32) {
        int c = g_counts[b * RES + v0 + threadIdx.x];
        inv[threadIdx.x] = 1.0f / (float)max(c, 1);
    }

    const float2* base = reinterpret_cast<const float2*>(
        g_featT + ((size_t)(b << 16) << 6));
    #pragma unroll
    for (int q = 0; q < 4; q++) {
        int vl = (w << 2) + q;                     // local voxel 0..31
        int vv = b * RES + v0 + vl;
        int start = g_offset[vv];
        int cnt   = g_counts[vv];
        float ax = 0.f, ay = 0.f, bx = 0.f, by = 0.f;
        int r = start;
        for (; r + 1 < start + cnt; r += 2) {
            float2 u0 = base[(size_t)r * 32 + lane];
            float2 u1 = base[(size_t)(r + 1) * 32 + lane];
            ax += u0.x; ay += u0.y;
            bx += u1.x; by += u1.y;
        }
        if (r < start + cnt) {
            float2 u0 = base[(size_t)r * 32 + lane];
            ax += u0.x; ay += u0.y;
        }
        tile[vl][(lane << 1) + 0] = ax + bx;
        tile[vl][(lane << 1) + 1] = ay + by;
    }
    __syncthreads();

    #pragma unroll
    for (int k = 0; k < 8; k++) {
        int c = w + (k << 3);                      // 0..63
        out[((size_t)(b * CHAN + c)) * RES + v0 + lane] = tile[lane][c] * inv[lane];
    }
}

// ---------------- launcher ---------------------------------------------------
extern "C" void kernel_launch(void* const* d_in, const int* in_sizes, int n_in,
                              void* d_out, int out_size) {
    const float* features = (const float*)d_in[0];  // [B, C, N]
    const float* coords   = (const float*)d_in[1];  // [B, 3, N]
    float* out = (float*)d_out;                     // [B,C,32,32,32] ++ [B,3,N]
    float* norm_out = out + (size_t)BATCH * CHAN * RES;

    zero_counts_kernel<<<512, 256>>>();

    dim3 grid_b(32, BATCH);
    mean_kernel<<<grid_b, 256>>>(coords);
    maxnorm_kernel<<<grid_b, 256>>>(coords);
    dim3 grid_p(128, BATCH);
    point_kernel<<<grid_p, 256>>>(coords, norm_out);

    scan_kernel<<<BATCH, 1024>>>();
    pos_kernel<<<BATCH * NPTS / 256, 256>>>();

    dim3 grid_t(NPTS / 64, BATCH);
    transposeT_kernel<<<grid_t, 256>>>(features);

    segreduce_kernel<<<BATCH * 1024, 256>>>(out);
}

// round 12
// speedup vs baseline: 1.1053x; 1.1053x over previous
#include <cuda_runtime.h>
#include <cuda_bf16.h>
#include <cstdint>

#define BATCH 16
#define CHAN  64
#define NPTS  65536
#define RES   (32*32*32)   // 32768

// ---------------- scratch (device globals; no allocations allowed) ----------
__device__ float        g_meansum[BATCH * 3];
__device__ unsigned int g_maxnorm[BATCH];          // float bits of max squared norm
__device__ int          g_voxidx[BATCH * NPTS];    // flat voxel index per point
__device__ int          g_counts[BATCH * RES];     // points per voxel
__device__ float        g_accum[(size_t)BATCH * RES * CHAN]; // [B, RES, C] sums

// ---------------- kernel 0: zero counts + stats ------------------------------
__global__ void zero_counts_kernel() {
    int i = blockIdx.x * blockDim.x + threadIdx.x;   // 131072 threads
    reinterpret_cast<int4*>(g_counts)[i] = make_int4(0, 0, 0, 0);
    if (i < BATCH * 3) g_meansum[i] = 0.0f;
    if (i < BATCH)     g_maxnorm[i] = 0u;
}

// ---------------- kernel 1: per-batch coordinate mean (sum) ------------------
__global__ void mean_kernel(const float* __restrict__ coords) {
    int b = blockIdx.y;
    const float* cb = coords + (size_t)b * 3 * NPTS;
    float sx = 0.f, sy = 0.f, sz = 0.f;
    for (int n = blockIdx.x * blockDim.x + threadIdx.x; n < NPTS;
         n += gridDim.x * blockDim.x) {
        sx += cb[n];
        sy += cb[NPTS + n];
        sz += cb[2 * NPTS + n];
    }
    for (int o = 16; o > 0; o >>= 1) {
        sx += __shfl_down_sync(0xffffffffu, sx, o);
        sy += __shfl_down_sync(0xffffffffu, sy, o);
        sz += __shfl_down_sync(0xffffffffu, sz, o);
    }
    __shared__ float shx[8], shy[8], shz[8];
    int warp = threadIdx.x >> 5, lane = threadIdx.x & 31;
    if (lane == 0) { shx[warp] = sx; shy[warp] = sy; shz[warp] = sz; }
    __syncthreads();
    if (threadIdx.x == 0) {
        float tx = 0.f, ty = 0.f, tz = 0.f;
        int nw = blockDim.x >> 5;
        for (int w = 0; w < nw; w++) { tx += shx[w]; ty += shy[w]; tz += shz[w]; }
        atomicAdd(&g_meansum[b * 3 + 0], tx);
        atomicAdd(&g_meansum[b * 3 + 1], ty);
        atomicAdd(&g_meansum[b * 3 + 2], tz);
    }
}

// ---------------- kernel 2: per-batch max squared norm -----------------------
__global__ void maxnorm_kernel(const float* __restrict__ coords) {
    int b = blockIdx.y;
    const float* cb = coords + (size_t)b * 3 * NPTS;
    const float inv_n = 1.0f / (float)NPTS;
    float mx = g_meansum[b * 3 + 0] * inv_n;
    float my = g_meansum[b * 3 + 1] * inv_n;
    float mz = g_meansum[b * 3 + 2] * inv_n;
    float best = 0.f;
    for (int n = blockIdx.x * blockDim.x + threadIdx.x; n < NPTS;
         n += gridDim.x * blockDim.x) {
        float dx = cb[n] - mx;
        float dy = cb[NPTS + n] - my;
        float dz = cb[2 * NPTS + n] - mz;
        best = fmaxf(best, dx * dx + dy * dy + dz * dz);
    }
    for (int o = 16; o > 0; o >>= 1)
        best = fmaxf(best, __shfl_down_sync(0xffffffffu, best, o));
    __shared__ float sh[8];
    int warp = threadIdx.x >> 5, lane = threadIdx.x & 31;
    if (lane == 0) sh[warp] = best;
    __syncthreads();
    if (threadIdx.x == 0) {
        float t = 0.f;
        int nw = blockDim.x >> 5;
        for (int w = 0; w < nw; w++) t = fmaxf(t, sh[w]);
        atomicMax(&g_maxnorm[b], __float_as_uint(t)); // nonneg floats: uint order ok
    }
}

// ---------------- kernel 3: per-point normalize, norm_coords, voxidx, count --
__global__ void point_kernel(const float* __restrict__ coords,
                             float* __restrict__ norm_out) {
    int b = blockIdx.y;
    const float* cb = coords + (size_t)b * 3 * NPTS;
    float* nb = norm_out + (size_t)b * 3 * NPTS;
    const float inv_n = 1.0f / (float)NPTS;
    float mx = g_meansum[b * 3 + 0] * inv_n;
    float my = g_meansum[b * 3 + 1] * inv_n;
    float mz = g_meansum[b * 3 + 2] * inv_n;
    float inv_d = 1.0f / (sqrtf(__uint_as_float(g_maxnorm[b])) * 2.0f);

    for (int n = blockIdx.x * blockDim.x + threadIdx.x; n < NPTS;
         n += gridDim.x * blockDim.x) {
        float sx = ((cb[n]            - mx) * inv_d + 0.5f) * 32.0f;
        float sy = ((cb[NPTS + n]     - my) * inv_d + 0.5f) * 32.0f;
        float sz = ((cb[2 * NPTS + n] - mz) * inv_d + 0.5f) * 32.0f;
        sx = fminf(fmaxf(sx, 0.0f), 31.0f);
        sy = fminf(fmaxf(sy, 0.0f), 31.0f);
        sz = fminf(fmaxf(sz, 0.0f), 31.0f);
        nb[n]            = sx;
        nb[NPTS + n]     = sy;
        nb[2 * NPTS + n] = sz;
        int vx = (int)rintf(sx);   // round-half-even, matches jnp.round
        int vy = (int)rintf(sy);
        int vz = (int)rintf(sz);
        int idx = (vx << 10) + (vy << 5) + vz;
        g_voxidx[(b << 16) + n] = idx;
        atomicAdd(&g_counts[b * RES + idx], 1);
    }
}

// ---------------- kernel 4: zero ONLY occupied voxels (installs hot set) -----
__global__ void zero_hot_kernel() {
    int g = blockIdx.x * blockDim.x + threadIdx.x;   // BATCH*RES threads
    if (g_counts[g] > 0) {
        float4* p = reinterpret_cast<float4*>(g_accum + ((size_t)g << 6));
        float4 z = make_float4(0.f, 0.f, 0.f, 0.f);
        #pragma unroll
        for (int k = 0; k < 16; k++) p[k] = z;
    }
}

// ---------------- kernel 5: scatter with v4 vector atomics -------------------
// thread = (b, cg, n); warp lanes share (b,cg), consecutive n.
__global__ void scatter_kernel(const float* __restrict__ features) {
    int tid = blockIdx.x * blockDim.x + threadIdx.x;  // 16,777,216 threads
    int n  = tid & (NPTS - 1);
    int g  = tid >> 16;            // b*16 + cg
    int cg = g & 15;
    int b  = g >> 4;

    const float* f = features + ((size_t)(b * CHAN + cg * 4)) * NPTS + n;
    float f0 = f[0];
    float f1 = f[NPTS];
    float f2 = f[2 * NPTS];
    float f3 = f[3 * NPTS];

    int v = g_voxidx[(b << 16) + n];
    float* dst = g_accum + (((size_t)(b * RES + v)) << 6) + (cg << 2);
    asm volatile("red.global.add.v4.f32 [%0], {%1, %2, %3, %4};"
                 :: "l"(dst), "f"(f0), "f"(f1), "f"(f2), "f"(f3)
                 : "memory");
}

// ---------------- kernel 6: transpose (sparse reads) + divide ----------------
__global__ void transpose_kernel(float* __restrict__ out) {
    __shared__ float tile[32][65];
    __shared__ float inv[32];
    __shared__ int   cnts[32];
    int chunk = blockIdx.x;            // 0 .. BATCH*1024-1
    int b  = chunk >> 10;
    int v0 = (chunk & 1023) << 5;      // 32-voxel group

    if (threadIdx.x < 32) {
        int c = g_counts[b * RES + v0 + threadIdx.x];
        cnts[threadIdx.x] = c;
        inv[threadIdx.x] = 1.0f / (float)max(c, 1);
    }
    __syncthreads();

    const float4* src = reinterpret_cast<const float4*>(
        g_accum + (((size_t)(b * RES + v0)) << 6));
    const float4 z4 = make_float4(0.f, 0.f, 0.f, 0.f);
    #pragma unroll
    for (int k = 0; k < 2; k++) {
        int idx = threadIdx.x + (k << 8);   // 0..511 (32 vox x 16 float4)
        int vl = idx >> 4;
        int c4 = idx & 15;
        float4 val = (cnts[vl] > 0) ? src[vl * 16 + c4] : z4;  // skip empty reads
        int c = c4 << 2;
        tile[vl][c + 0] = val.x;
        tile[vl][c + 1] = val.y;
        tile[vl][c + 2] = val.z;
        tile[vl][c + 3] = val.w;
    }
    __syncthreads();

    int lane = threadIdx.x & 31;
    int wrp  = threadIdx.x >> 5;
    #pragma unroll
    for (int k = 0; k < 8; k++) {
        int c = wrp + (k << 3);            // 0..63
        out[((size_t)(b * CHAN + c)) * RES + v0 + lane] = tile[lane][c] * inv[lane];
    }
}

// ---------------- launcher ---------------------------------------------------
extern "C" void kernel_launch(void* const* d_in, const int* in_sizes, int n_in,
                              void* d_out, int out_size) {
    const float* features = (const float*)d_in[0];  // [B, C, N]
    const float* coords   = (const float*)d_in[1];  // [B, 3, N]
    float* out = (float*)d_out;                     // [B,C,32,32,32] ++ [B,3,N]
    float* norm_out = out + (size_t)BATCH * CHAN * RES;

    zero_counts_kernel<<<512, 256>>>();

    dim3 grid_b(32, BATCH);
    mean_kernel<<<grid_b, 256>>>(coords);
    maxnorm_kernel<<<grid_b, 256>>>(coords);
    dim3 grid_p(128, BATCH);
    point_kernel<<<grid_p, 256>>>(coords, norm_out);

    zero_hot_kernel<<<BATCH * RES / 256, 256>>>();  // ~8MB, installs L2 hot set
    scatter_kernel<<<65536, 256>>>(features);       // 16.8M threads, v4 reds

    transpose_kernel<<<BATCH * 1024, 256>>>(out);
}